// round 17
// baseline (speedup 1.0000x reference)
#include <cuda_runtime.h>
#include <cuda_fp16.h>
#include <math.h>

#define BB   64
#define NN   512
#define FIN  256
#define DD   128
#define KTOP 20
#define HIDN 512

// ---- scratch (device globals; no allocations) ----
static __device__ __half d_xl16[BB*NN*DD];     // [b,n,d] lin(x), fp16
static __device__ __half d_gT16[BB*DD*NN];     // [b,d,n] gated GCN output (transposed), fp16
static __device__ __half d_w12T[NN*HIDN];      // [n][h2] = sum_h w1[h,n]*w2[h2,h], fp16
static __device__ float  d_p [BB*NN];
static __device__ float  d_q [BB*NN];
static __device__ float  d_rinv[NN];
static __device__ float  d_r [NN];
static __device__ float  d_s [NN];
static __device__ float  d_cosm[NN*NN];
static __device__ int    d_topk[NN*KTOP];

// ---------------- MMA / cp.async / ldmatrix helpers ----------------
__device__ __forceinline__ void mma_tf32(float c[4],
        unsigned a0, unsigned a1, unsigned a2, unsigned a3,
        unsigned b0, unsigned b1) {
    asm volatile(
        "mma.sync.aligned.m16n8k8.row.col.f32.tf32.tf32.f32 "
        "{%0,%1,%2,%3}, {%4,%5,%6,%7}, {%8,%9}, {%0,%1,%2,%3};\n"
        : "+f"(c[0]), "+f"(c[1]), "+f"(c[2]), "+f"(c[3])
        : "r"(a0), "r"(a1), "r"(a2), "r"(a3), "r"(b0), "r"(b1));
}
__device__ __forceinline__ void mma_f16(float c[4],
        unsigned a0, unsigned a1, unsigned a2, unsigned a3,
        unsigned b0, unsigned b1) {
    asm volatile(
        "mma.sync.aligned.m16n8k16.row.col.f32.f16.f16.f32 "
        "{%0,%1,%2,%3}, {%4,%5,%6,%7}, {%8,%9}, {%0,%1,%2,%3};\n"
        : "+f"(c[0]), "+f"(c[1]), "+f"(c[2]), "+f"(c[3])
        : "r"(a0), "r"(a1), "r"(a2), "r"(a3), "r"(b0), "r"(b1));
}
__device__ __forceinline__ void ldsm_x4(unsigned& r0, unsigned& r1,
                                        unsigned& r2, unsigned& r3, unsigned addr) {
    asm volatile("ldmatrix.sync.aligned.m8n8.x4.shared.b16 {%0,%1,%2,%3}, [%4];"
        : "=r"(r0), "=r"(r1), "=r"(r2), "=r"(r3) : "r"(addr));
}
__device__ __forceinline__ void ldsm_x2t(unsigned& r0, unsigned& r1, unsigned addr) {
    asm volatile("ldmatrix.sync.aligned.m8n8.x2.trans.shared.b16 {%0,%1}, [%2];"
        : "=r"(r0), "=r"(r1) : "r"(addr));
}
__device__ __forceinline__ void cpa16(void* dst, const void* src) {
    unsigned ds = (unsigned)__cvta_generic_to_shared(dst);
    asm volatile("cp.async.cg.shared.global [%0], [%1], 16;" :: "r"(ds), "l"(src));
}
#define CP_COMMIT asm volatile("cp.async.commit_group;")
#define CP_WAIT1  asm volatile("cp.async.wait_group 1;")
#define CP_WAIT0  asm volatile("cp.async.wait_group 0;")
#define NSTAGE    3

// ---- tf32 k_xl geometry ----
#define A_KN_WORDS 4352          // [32 k][136]
#define B_KN_WORDS 4608          // [128][36]
#define STG_KN     (A_KN_WORDS + B_KN_WORDS)   // 8960 w

// ---- W12 (tf32) geometry: 64(n) x 128(h2) tiles, K-chunk 32 ----
#define W12_A_W  2304            // [32 k][72w]
#define W12_STG  6912            // + [128][36w]

// ---- final gemm geometry ----
#define GF_A_W   4608            // A: [128 d][36w] (72 halves, 144 B pitch)
#define GF_B_W   4352            // B: [64 k][68w]  (136 halves, 272 B pitch)
#define GF_STG   (GF_A_W + GF_B_W)   // 8960 w

// tf32 chunk (128m): A [k][136], B [m][36]
#define CHUNK_KN(pA, pB)                                                        \
    _Pragma("unroll")                                                            \
    for (int ks = 0; ks < 4; ks++) {                                             \
        int k8 = ks*8;                                                           \
        unsigned af[4][4], bf[4][2];                                             \
        _Pragma("unroll")                                                        \
        for (int mi = 0; mi < 4; mi++) {                                         \
            int r = wm + mi*16 + g;                                              \
            af[mi][0] = (pA)[(k8+t4  )*136 + r    ];                             \
            af[mi][1] = (pA)[(k8+t4  )*136 + r + 8];                             \
            af[mi][2] = (pA)[(k8+t4+4)*136 + r    ];                             \
            af[mi][3] = (pA)[(k8+t4+4)*136 + r + 8];                             \
        }                                                                        \
        _Pragma("unroll")                                                        \
        for (int ni = 0; ni < 4; ni++) {                                         \
            int rn = wn + ni*8 + g;                                              \
            bf[ni][0] = (pB)[rn*36 + k8+t4    ];                                 \
            bf[ni][1] = (pB)[rn*36 + k8+t4 + 4];                                 \
        }                                                                        \
        _Pragma("unroll")                                                        \
        for (int mi = 0; mi < 4; mi++)                                           \
            _Pragma("unroll")                                                    \
            for (int ni = 0; ni < 4; ni++)                                       \
                mma_tf32(c[mi][ni], af[mi][0], af[mi][1], af[mi][2],             \
                         af[mi][3], bf[ni][0], bf[ni][1]);                       \
    }

// ---------------------------------------------------------------
// K_misc: fused norm + pack
// ---------------------------------------------------------------
__global__ void __launch_bounds__(256) k_misc(const float* __restrict__ emb,
                                              const float* __restrict__ aei,
                                              const float* __restrict__ aej,
                                              float* __restrict__ out) {
    int blk = blockIdx.x, tid = threadIdx.x;
    if (blk < 256) {
        int half = tid >> 7, t = tid & 127;
        int n = blk*2 + half;
        float w  = emb[n*DD + t];
        float v0 = w*w, v1 = w*aei[t], v2 = w*aej[t];
        #pragma unroll
        for (int o = 16; o; o >>= 1) {
            v0 += __shfl_xor_sync(0xffffffffu, v0, o);
            v1 += __shfl_xor_sync(0xffffffffu, v1, o);
            v2 += __shfl_xor_sync(0xffffffffu, v2, o);
        }
        __shared__ float s0[2][4], s1[2][4], s2[2][4];
        int wid = t >> 5, lane = t & 31;
        if (lane == 0) { s0[half][wid]=v0; s1[half][wid]=v1; s2[half][wid]=v2; }
        __syncthreads();
        if (t == 0) {
            d_rinv[n] = rsqrtf(s0[half][0]+s0[half][1]+s0[half][2]+s0[half][3]);
            d_r[n] = s1[half][0]+s1[half][1]+s1[half][2]+s1[half][3];
            d_s[n] = s2[half][0]+s2[half][1]+s2[half][2]+s2[half][3];
        }
    } else {
        int i = (blk - 256)*256 + tid;
        const int OUT0 = BB*DD*HIDN;
        if (i < NN*DD) out[OUT0 + i] = emb[i];
    }
}

// ---------------------------------------------------------------
// K_w12 (tf32): W12T[n][h2] = sum_h w1[h,n] * w2[h2,h]
//   32 CTAs; own stream — genuinely overlaps the small kernels.
// ---------------------------------------------------------------
__global__ void __launch_bounds__(256) k_w12(const float* __restrict__ w1,
                                             const float* __restrict__ w2) {
    extern __shared__ unsigned smu[];
    int h20 = blockIdx.x * 128, n0 = blockIdx.y * 64;
    int tid = threadIdx.x;
    int w = tid >> 5, lane = tid & 31;
    int g = lane >> 2, t4 = lane & 3;
    int wm = (w & 1) * 32, wn = (w >> 1) * 32;
    float c[2][4][4] = {};

    #define W_LOAD(st, k0)                                                       \
        {                                                                        \
            unsigned* pA = smu + (st)*W12_STG;                                   \
            unsigned* pB = pA + W12_A_W;                                         \
            _Pragma("unroll")                                                    \
            for (int a = 0; a < 2; a++) {                                        \
                int idx = tid + a*256;                                           \
                int kk = idx >> 4, n4 = idx & 15;                                \
                cpa16(pA + kk*72 + n4*4, w1 + (size_t)((k0)+kk)*NN + n0 + n4*4); \
            }                                                                    \
            _Pragma("unroll")                                                    \
            for (int a = 0; a < 4; a++) {                                        \
                int idx = tid + a*256;                                           \
                int dd = idx >> 3, k4 = idx & 7;                                 \
                cpa16(pB + dd*36 + k4*4, w2 + (size_t)(h20+dd)*HIDN + (k0) + k4*4); \
            }                                                                    \
        }

    W_LOAD(0, 0) CP_COMMIT;
    W_LOAD(1, 32) CP_COMMIT;
    #pragma unroll 1
    for (int it = 0; it < HIDN/32; it++) {
        if (it + 1 < HIDN/32) { CP_WAIT1; } else { CP_WAIT0; }
        __syncthreads();
        if (it + 2 < HIDN/32) { W_LOAD((it+2)%NSTAGE, (it+2)*32) CP_COMMIT; }
        unsigned* pA = smu + (it%NSTAGE)*W12_STG;
        unsigned* pB = pA + W12_A_W;
        #pragma unroll
        for (int ks = 0; ks < 4; ks++) {
            int k8 = ks*8;
            unsigned af[2][4], bf[4][2];
            #pragma unroll
            for (int mi = 0; mi < 2; mi++) {
                int r = wm + mi*16 + g;
                af[mi][0] = pA[(k8+t4  )*72 + r    ];
                af[mi][1] = pA[(k8+t4  )*72 + r + 8];
                af[mi][2] = pA[(k8+t4+4)*72 + r    ];
                af[mi][3] = pA[(k8+t4+4)*72 + r + 8];
            }
            #pragma unroll
            for (int ni = 0; ni < 4; ni++) {
                int rn = wn + ni*8 + g;
                bf[ni][0] = pB[rn*36 + k8+t4    ];
                bf[ni][1] = pB[rn*36 + k8+t4 + 4];
            }
            #pragma unroll
            for (int mi = 0; mi < 2; mi++)
                #pragma unroll
                for (int ni = 0; ni < 4; ni++)
                    mma_tf32(c[mi][ni], af[mi][0], af[mi][1], af[mi][2],
                             af[mi][3], bf[ni][0], bf[ni][1]);
        }
    }
    #undef W_LOAD
    #pragma unroll
    for (int mi = 0; mi < 2; mi++)
        #pragma unroll
        for (int ni = 0; ni < 4; ni++) {
            int row = n0 + wm + mi*16 + g, col = h20 + wn + ni*8 + t4*2;
            *(__half2*)&d_w12T[(size_t)(row    )*HIDN + col] =
                __floats2half2_rn(c[mi][ni][0], c[mi][ni][1]);
            *(__half2*)&d_w12T[(size_t)(row + 8)*HIDN + col] =
                __floats2half2_rn(c[mi][ni][2], c[mi][ni][3]);
        }
}

// ---------------------------------------------------------------
// K1: cosine matrix — 32(i) x 64(j) tiles, grid (8,16)
// ---------------------------------------------------------------
__global__ void __launch_bounds__(256) k_cos(const float* __restrict__ emb) {
    __shared__ float sAt[32][36];
    __shared__ float sBt[32][68];
    int i0 = blockIdx.y * 32, j0 = blockIdx.x * 64;
    int tid = threadIdx.x;
    int tx = tid & 15, ty = tid >> 4;
    float c[2][4] = {};
    for (int k0 = 0; k0 < DD; k0 += 32) {
        #pragma unroll
        for (int a = 0; a < 4; a++) {
            int idx = tid + a*256;
            int row = idx >> 5, kk = idx & 31;
            sAt[kk][row] = emb[(i0+row)*DD + k0 + kk];
        }
        #pragma unroll
        for (int a = 0; a < 8; a++) {
            int idx = tid + a*256;
            int row = idx >> 5, kk = idx & 31;
            sBt[kk][row] = emb[(j0+row)*DD + k0 + kk];
        }
        __syncthreads();
        #pragma unroll
        for (int kk = 0; kk < 32; kk++) {
            float av[2], bv[4];
            *(float2*)av = *(const float2*)&sAt[kk][ty*2];
            *(float4*)bv = *(const float4*)&sBt[kk][tx*4];
            #pragma unroll
            for (int ii = 0; ii < 2; ii++)
                #pragma unroll
                for (int jj = 0; jj < 4; jj++)
                    c[ii][jj] += av[ii]*bv[jj];
        }
        __syncthreads();
    }
    float rj[4];
    #pragma unroll
    for (int jj = 0; jj < 4; jj++) rj[jj] = d_rinv[j0 + tx*4 + jj];
    #pragma unroll
    for (int ii = 0; ii < 2; ii++) {
        float ri = d_rinv[i0 + ty*2 + ii];
        float4 v;
        v.x = c[ii][0]*ri*rj[0]; v.y = c[ii][1]*ri*rj[1];
        v.z = c[ii][2]*ri*rj[2]; v.w = c[ii][3]*ri*rj[3];
        *(float4*)&d_cosm[(i0 + ty*2 + ii)*NN + j0 + tx*4] = v;
    }
}

// ---------------------------------------------------------------
// K2: top-20 per row — 2 warps/CTA, grid 256 (spread over all SMs)
// ---------------------------------------------------------------
__global__ void __launch_bounds__(64) k_topk(float* __restrict__ out, int mode) {
    int row  = blockIdx.x*2 + (threadIdx.x >> 5);
    int lane = threadIdx.x & 31;
    float v[16];
    #pragma unroll
    for (int j = 0; j < 16; j++) v[j] = d_cosm[row*NN + lane + 32*j];
    for (int t = 0; t < KTOP; t++) {
        float bv = v[0]; int bj = 0;
        #pragma unroll
        for (int j = 1; j < 16; j++)
            if (v[j] > bv) { bv = v[j]; bj = j; }
        int bidx = lane + 32*bj;
        #pragma unroll
        for (int o = 16; o; o >>= 1) {
            float ov = __shfl_xor_sync(0xffffffffu, bv, o);
            int   oi = __shfl_xor_sync(0xffffffffu, bidx, o);
            if (ov > bv || (ov == bv && oi < bidx)) { bv = ov; bidx = oi; }
        }
        if (lane == 0) {
            d_topk[row*KTOP + t] = bidx;
            if (mode) out[BB*DD*HIDN + NN*DD + row*KTOP + t] = (float)bidx;
        }
        #pragma unroll
        for (int j = 0; j < 16; j++)
            if (lane + 32*j == bidx) v[j] = -INFINITY;
    }
}

// ---------------------------------------------------------------
// K3: xl (tf32 MMA, 3-stage) + fused p/q epilogue.
// ---------------------------------------------------------------
__global__ void __launch_bounds__(256, 2) k_xl(const float* __restrict__ data,
                                               const float* __restrict__ linw,
                                               const float* __restrict__ ai,
                                               const float* __restrict__ aj) {
    extern __shared__ unsigned smu[];
    __shared__ float spq[DD][2];
    int b = blockIdx.y, n0 = blockIdx.x * 128;
    int tid = threadIdx.x;
    int w = tid >> 5, lane = tid & 31;
    int g = lane >> 2, t4 = lane & 3;
    int wm = (w & 1) * 64, wn = (w >> 1) * 32;
    if (tid < DD) { spq[tid][0] = 0.f; spq[tid][1] = 0.f; }
    float c[4][4][4] = {};

    #define XL_LOAD(st, f0)                                                      \
        {                                                                        \
            unsigned* pA = smu + (st)*STG_KN;                                    \
            unsigned* pB = pA + A_KN_WORDS;                                      \
            _Pragma("unroll")                                                    \
            for (int a = 0; a < 4; a++) {                                        \
                int idx = tid + a*256;                                           \
                int kk = idx >> 5, n4 = idx & 31;                                \
                cpa16(pA + kk*136 + n4*4,                                        \
                      data + ((size_t)b*FIN + (f0) + kk)*NN + n0 + n4*4);        \
            }                                                                    \
            _Pragma("unroll")                                                    \
            for (int a = 0; a < 4; a++) {                                        \
                int idx = tid + a*256;                                           \
                int dd = idx >> 3, k4 = idx & 7;                                 \
                cpa16(pB + dd*36 + k4*4, linw + dd*FIN + (f0) + k4*4);           \
            }                                                                    \
        }

    XL_LOAD(0, 0) CP_COMMIT;
    XL_LOAD(1, 32) CP_COMMIT;
    #pragma unroll 1
    for (int it = 0; it < FIN/32; it++) {
        if (it + 1 < FIN/32) { CP_WAIT1; } else { CP_WAIT0; }
        __syncthreads();
        if (it + 2 < FIN/32) { XL_LOAD((it+2)%NSTAGE, (it+2)*32) CP_COMMIT; }
        unsigned* pA = smu + (it%NSTAGE)*STG_KN;
        unsigned* pB = pA + A_KN_WORDS;
        CHUNK_KN(pA, pB)
    }
    #undef XL_LOAD

    float pv[8] = {}, qv[8] = {};
    #pragma unroll
    for (int mi = 0; mi < 4; mi++)
        #pragma unroll
        for (int ni = 0; ni < 4; ni++) {
            int row = n0 + wm + mi*16 + g, col = wn + ni*8 + t4*2;
            size_t i0 = ((size_t)b*NN + row    )*DD + col;
            size_t i1 = ((size_t)b*NN + row + 8)*DD + col;
            *(__half2*)&d_xl16[i0] = __floats2half2_rn(c[mi][ni][0], c[mi][ni][1]);
            *(__half2*)&d_xl16[i1] = __floats2half2_rn(c[mi][ni][2], c[mi][ni][3]);
            float a0 = ai[col], a1 = ai[col+1];
            float j0 = aj[col], j1 = aj[col+1];
            pv[mi*2  ] += c[mi][ni][0]*a0 + c[mi][ni][1]*a1;
            pv[mi*2+1] += c[mi][ni][2]*a0 + c[mi][ni][3]*a1;
            qv[mi*2  ] += c[mi][ni][0]*j0 + c[mi][ni][1]*j1;
            qv[mi*2+1] += c[mi][ni][2]*j0 + c[mi][ni][3]*j1;
        }
    #pragma unroll
    for (int r = 0; r < 8; r++) {
        pv[r] += __shfl_xor_sync(0xffffffffu, pv[r], 1);
        pv[r] += __shfl_xor_sync(0xffffffffu, pv[r], 2);
        qv[r] += __shfl_xor_sync(0xffffffffu, qv[r], 1);
        qv[r] += __shfl_xor_sync(0xffffffffu, qv[r], 2);
    }
    if (t4 == 0) {
        #pragma unroll
        for (int mi = 0; mi < 4; mi++) {
            int r0 = wm + mi*16 + g;
            atomicAdd(&spq[r0][0],   pv[mi*2]);
            atomicAdd(&spq[r0][1],   qv[mi*2]);
            atomicAdd(&spq[r0+8][0], pv[mi*2+1]);
            atomicAdd(&spq[r0+8][1], qv[mi*2+1]);
        }
    }
    __syncthreads();
    if (tid < 2*DD) {
        int row = tid >> 1, which = tid & 1;
        float v = spq[row][which];
        if (which == 0) d_p[b*NN + n0 + row] = v;
        else            d_q[b*NN + n0 + row] = v;
    }
}

// ---------------------------------------------------------------
// K5: attention with smem-cached xl16 batch slice + gts staging.
// ---------------------------------------------------------------
#define GTS_PITCH 264
__global__ void __launch_bounds__(256, 1) k_attn2(const float* __restrict__ emb,
                                                  const float* __restrict__ gbias,
                                                  const float* __restrict__ gamma,
                                                  const float* __restrict__ beta) {
    extern __shared__ __half smh[];
    __half* xlc = smh;                 // [512][128] fp16 = 131072 B
    __half* gts = smh + NN*DD;         // [128][GTS_PITCH] = 67584 B
    int b = blockIdx.x >> 1, nhalf = blockIdx.x & 1;
    int n0 = nhalf * 256;
    int tid = threadIdx.x, wrp = tid >> 5, lane = tid & 31;

    const __half* src = d_xl16 + (size_t)b*NN*DD;
    #pragma unroll
    for (int a = 0; a < 32; a++) {
        int idx = tid + a*256;
        cpa16(xlc + idx*8, src + idx*8);
    }
    CP_COMMIT; CP_WAIT0;
    __syncthreads();

    const float inv = rsqrtf(1.0f + 1e-5f);
    for (int i = 0; i < 32; i++) {
        int n = n0 + wrp*32 + i;
        int widx = b*NN + n;
        int src_k = 0; float alpha = -1e30f;
        if (lane < KTOP) {
            src_k = d_topk[n*KTOP + lane];
            alpha = d_p[widx] + d_r[n] + d_q[b*NN + src_k] + d_s[src_k];
            alpha = alpha > 0.f ? alpha : 0.2f*alpha;
        }
        float m = alpha;
        #pragma unroll
        for (int o = 16; o; o >>= 1) m = fmaxf(m, __shfl_xor_sync(0xffffffffu, m, o));
        float ex = (lane < KTOP) ? __expf(alpha - m) : 0.f;
        float sm = ex;
        #pragma unroll
        for (int o = 16; o; o >>= 1) sm += __shfl_xor_sync(0xffffffffu, sm, o);
        float aw = __fdividef(ex, sm);

        float2 acc0 = {0.f,0.f}, acc1 = {0.f,0.f};
        #pragma unroll
        for (int k = 0; k < KTOP; k++) {
            int   sk = __shfl_sync(0xffffffffu, src_k, k);
            float ak = __shfl_sync(0xffffffffu, aw,  k);
            const __half2* xr = (const __half2*)(xlc + sk*DD);
            float2 f0 = __half22float2(xr[lane]);
            float2 f1 = __half22float2(xr[lane + 32]);
            acc0.x += ak*f0.x; acc0.y += ak*f0.y;
            acc1.x += ak*f1.x; acc1.y += ak*f1.y;
        }
        int d0 = 2*lane, d1 = 2*lane + 64;
        float h0 = fmaxf((acc0.x + gbias[d0  ])*(gamma[d0  ]*inv) + beta[d0  ], 0.f) * emb[n*DD + d0];
        float h1 = fmaxf((acc0.y + gbias[d0+1])*(gamma[d0+1]*inv) + beta[d0+1], 0.f) * emb[n*DD + d0+1];
        float h2 = fmaxf((acc1.x + gbias[d1  ])*(gamma[d1  ]*inv) + beta[d1  ], 0.f) * emb[n*DD + d1];
        float h3 = fmaxf((acc1.y + gbias[d1+1])*(gamma[d1+1]*inv) + beta[d1+1], 0.f) * emb[n*DD + d1+1];
        int nn = n - n0;
        gts[(d0  )*GTS_PITCH + nn] = __float2half(h0);
        gts[(d0+1)*GTS_PITCH + nn] = __float2half(h1);
        gts[(d1  )*GTS_PITCH + nn] = __float2half(h2);
        gts[(d1+1)*GTS_PITCH + nn] = __float2half(h3);
    }
    __syncthreads();
    for (int row = wrp; row < DD; row += 8) {
        *(uint4*)(d_gT16 + ((size_t)b*DD + row)*NN + n0 + lane*8) =
            *(uint4*)(gts + row*GTS_PITCH + lane*8);
    }
}

// ---------------------------------------------------------------
// K_gfin (fp16 MMA): out[b,d,h2] = sigmoid(sum_n gT[b,d,n]*W12T[n,h2] + b2)
// ---------------------------------------------------------------
__global__ void __launch_bounds__(256, 2) k_gfin(const float* __restrict__ b2,
                                                 float* __restrict__ out) {
    extern __shared__ unsigned smu[];
    int b = blockIdx.y, h20 = blockIdx.x * 128;
    int tid = threadIdx.x;
    int w = tid >> 5, lane = tid & 31;
    int g = lane >> 2, t4 = lane & 3;
    int wm = (w & 1) * 64, wn = (w >> 1) * 32;
    unsigned smemBase = (unsigned)__cvta_generic_to_shared(smu);
    float c[4][4][4] = {};

    #define GF_LOAD(st, k0)                                                      \
        {                                                                        \
            unsigned* pA = smu + (st)*GF_STG;                                    \
            unsigned* pB = pA + GF_A_W;                                          \
            _Pragma("unroll")                                                    \
            for (int a = 0; a < 4; a++) {                                        \
                int idx = tid + a*256;                                           \
                int row = idx >> 3, seg = idx & 7;                               \
                cpa16(pA + row*36 + seg*4,                                       \
                      d_gT16 + ((size_t)b*DD + row)*NN + (k0) + seg*8);          \
            }                                                                    \
            _Pragma("unroll")                                                    \
            for (int a = 0; a < 4; a++) {                                        \
                int idx = tid + a*256;                                           \
                int row = idx >> 4, seg = idx & 15;                              \
                cpa16(pB + row*68 + seg*4,                                       \
                      d_w12T + (size_t)((k0)+row)*HIDN + h20 + seg*8);           \
            }                                                                    \
        }

    GF_LOAD(0, 0) CP_COMMIT;
    GF_LOAD(1, 64) CP_COMMIT;
    #pragma unroll 1
    for (int it = 0; it < NN/64; it++) {
        if (it + 1 < NN/64) { CP_WAIT1; } else { CP_WAIT0; }
        __syncthreads();
        if (it + 2 < NN/64) { GF_LOAD((it+2)%NSTAGE, (it+2)*64) CP_COMMIT; }
        unsigned aB = smemBase + ((it%NSTAGE)*GF_STG)*4;
        unsigned bB = aB + GF_A_W*4;
        unsigned aRow = ((lane>>3)&1)*8 + (lane&7);
        unsigned aK   = (lane>>4)*16;
        unsigned bR   = lane & 15;
        #pragma unroll
        for (int ks = 0; ks < 4; ks++) {
            unsigned af[4][4], bf[4][2];
            #pragma unroll
            for (int mi = 0; mi < 4; mi++)
                ldsm_x4(af[mi][0], af[mi][1], af[mi][2], af[mi][3],
                        aB + (wm + mi*16 + aRow)*144 + ks*32 + aK);
            #pragma unroll
            for (int ni = 0; ni < 4; ni++)
                ldsm_x2t(bf[ni][0], bf[ni][1],
                         bB + (ks*16 + bR)*272 + (wn + ni*8)*2);
            #pragma unroll
            for (int mi = 0; mi < 4; mi++)
                #pragma unroll
                for (int ni = 0; ni < 4; ni++)
                    mma_f16(c[mi][ni], af[mi][0], af[mi][1], af[mi][2],
                            af[mi][3], bf[ni][0], bf[ni][1]);
        }
    }
    #undef GF_LOAD
    #pragma unroll
    for (int mi = 0; mi < 4; mi++)
        #pragma unroll
        for (int ni = 0; ni < 4; ni++) {
            int row = wm + mi*16 + g, col = h20 + wn + ni*8 + t4*2;
            float bb0 = b2[col], bb1 = b2[col + 1];
            float2 v0, v1;
            v0.x = __fdividef(1.0f, 1.0f + __expf(-(c[mi][ni][0] + bb0)));
            v0.y = __fdividef(1.0f, 1.0f + __expf(-(c[mi][ni][1] + bb1)));
            v1.x = __fdividef(1.0f, 1.0f + __expf(-(c[mi][ni][2] + bb0)));
            v1.y = __fdividef(1.0f, 1.0f + __expf(-(c[mi][ni][3] + bb1)));
            *(float2*)&out[((size_t)b*DD + row    )*HIDN + col] = v0;
            *(float2*)&out[((size_t)b*DD + row + 8)*HIDN + col] = v1;
        }
}

extern "C" void kernel_launch(void* const* d_in, const int* in_sizes, int n_in,
                              void* d_out, int out_size) {
    const float* data  = (const float*)d_in[0];
    const float* emb   = (const float*)d_in[1];
    const float* linw  = (const float*)d_in[2];
    const float* ai    = (const float*)d_in[3];
    const float* aj    = (const float*)d_in[4];
    const float* aei   = (const float*)d_in[5];
    const float* aej   = (const float*)d_in[6];
    const float* gbias = (const float*)d_in[7];
    const float* gamma = (const float*)d_in[8];
    const float* beta  = (const float*)d_in[9];
    const float* w1    = (const float*)d_in[10];
    const float* w2    = (const float*)d_in[11];
    const float* b2    = (const float*)d_in[12];
    float* out = (float*)d_out;

    static cudaStream_t s3 = nullptr;
    static cudaEvent_t evFork = nullptr, evW12 = nullptr;
    static bool init_done = false;
    const int smem_kn   = NSTAGE*STG_KN*4;           // 107520 B
    const int smem_gf   = NSTAGE*GF_STG*4;           // 107520 B
    const int smem_w12  = NSTAGE*W12_STG*4;          // 82944 B
    const int smem_attn = (NN*DD + DD*GTS_PITCH)*2;  // 198656 B
    if (!init_done) {
        cudaFuncSetAttribute(k_xl,    cudaFuncAttributeMaxDynamicSharedMemorySize, smem_kn);
        cudaFuncSetAttribute(k_gfin,  cudaFuncAttributeMaxDynamicSharedMemorySize, smem_gf);
        cudaFuncSetAttribute(k_w12,   cudaFuncAttributeMaxDynamicSharedMemorySize, smem_w12);
        cudaFuncSetAttribute(k_attn2, cudaFuncAttributeMaxDynamicSharedMemorySize, smem_attn);
        cudaStreamCreateWithFlags(&s3, cudaStreamNonBlocking);
        cudaEventCreateWithFlags(&evFork, cudaEventDisableTiming);
        cudaEventCreateWithFlags(&evW12,  cudaEventDisableTiming);
        init_done = true;
    }

    const int OUT0 = BB*DD*HIDN;
    int tail = (out_size >= OUT0 + NN*DD) ? 1 : 0;
    int mode = (out_size >= OUT0 + NN*DD + NN*KTOP) ? 1 : 0;

    // s3: W12 (inputs only; 32 CTAs) —真 overlap with the small kernels
    cudaEventRecord(evFork, 0);
    cudaStreamWaitEvent(s3, evFork, 0);
    k_w12<<<dim3(4, 8), 256, smem_w12, s3>>>(w1, w2);
    cudaEventRecord(evW12, s3);

    // main stream: explicit serial dependency order, no fake overlap
    int misc_blocks = 256 + (tail ? 256 : 0);
    k_misc<<<misc_blocks, 256>>>(emb, aei, aej, out);
    k_cos <<<dim3(8, 16), 256>>>(emb);
    k_topk<<<NN/2, 64>>>(out, mode);
    k_xl<<<dim3(4, BB), 256, smem_kn>>>(data, linw, ai, aj);
    k_attn2<<<2*BB, 256, smem_attn>>>(emb, gbias, gamma, beta);
    cudaStreamWaitEvent(0, evW12, 0);
    k_gfin<<<dim3(4, BB), 256, smem_gf>>>(b2, out);
}